// round 14
// baseline (speedup 1.0000x reference)
#include <cuda_runtime.h>
#include <math.h>
#include <stdint.h>

#define N_NODES 50000
#define IN_DIM  27
#define F1      256
#define H1      4
#define F2      128
#define H2      2

// ---------------- scratch (no allocations allowed) ----------------
__device__ float g_h1  [N_NODES * F1];
__device__ float g_agg1[N_NODES * (F1 + H1)];   // agg1 + z1 appended
__device__ float g_h2  [N_NODES * F2];
__device__ float g_agg2[N_NODES * (F2 + H2)];   // agg2 + z2 appended
__device__ float g_ss  [N_NODES * H1];
__device__ float g_sd  [N_NODES * H1];

__device__ __forceinline__ void red_add_f4(float* p, float4 v) {
    asm volatile("red.global.add.v4.f32 [%0], {%1, %2, %3, %4};"
                 :: "l"(p), "f"(v.x), "f"(v.y), "f"(v.z), "f"(v.w) : "memory");
}

__device__ __forceinline__ float elu_fast(float v) {
    return (v > 0.f) ? v : (__expf(v) - 1.f);
}

__device__ __forceinline__ uint32_t smem_u32(const void* p) {
    uint32_t a;
    asm("{ .reg .u64 t; cvta.to.shared.u64 t, %1; cvt.u32.u64 %0, t; }" : "=r"(a) : "l"(p));
    return a;
}

// packed f32x2 helpers (plain sm_100+ PTX, not an 'a' feature)
__device__ __forceinline__ unsigned long long rep2(float x) {
    unsigned long long r;
    asm("mov.b64 %0, {%1, %1};" : "=l"(r) : "f"(x));
    return r;
}
__device__ __forceinline__ void unpack2(unsigned long long v, float& a, float& b) {
    asm("mov.b64 {%0, %1}, %2;" : "=f"(a), "=f"(b) : "l"(v));
}
#define FMA2(d, a, b) \
    asm("fma.rn.f32x2 %0, %1, %2, %0;" : "+l"(d) : "l"(a), "l"(b))

#define CP_ASYNC16(dst, src) \
    asm volatile("cp.async.cg.shared.global [%0], [%1], 16;" :: "r"(dst), "l"(src))
#define CP_COMMIT() asm volatile("cp.async.commit_group;")
#define CP_WAIT0()  asm volatile("cp.async.wait_group 0;" ::: "memory")

// ---------------- GEMM1 (f32x2 row pairs): x[N,27] @ W1[27,256] -> h1[N,256] ----------------
__global__ void __launch_bounds__(256)
gemm1_kernel(const float* __restrict__ x,
             const float* __restrict__ W,
             float* __restrict__ out) {
    __shared__ float Ws[IN_DIM * F1];       // 27KB
    __shared__ float xs[IN_DIM * 64];       // transposed: xs[k][r]
    int t = threadIdx.x;                    // 256 threads
    for (int i = t; i < IN_DIM * F1; i += 256) Ws[i] = W[i];
    int r0 = blockIdx.x * 64;
    for (int i = t; i < IN_DIM * 64; i += 256) {
        int k = i >> 6, r = i & 63;
        int gr = r0 + r;
        xs[k * 64 + r] = (gr < N_NODES) ? x[gr * IN_DIM + k] : 0.f;
    }
    __syncthreads();

    unsigned long long w2[IN_DIM];
#pragma unroll
    for (int k = 0; k < IN_DIM; k++) w2[k] = rep2(Ws[k * F1 + t]);

#pragma unroll 4
    for (int p = 0; p < 32; p++) {          // row pair (2p, 2p+1)
        unsigned long long acc = 0ULL;
#pragma unroll
        for (int k = 0; k < IN_DIM; k++) {
            unsigned long long xp = *(const unsigned long long*)&xs[k * 64 + 2 * p];
            FMA2(acc, xp, w2[k]);
        }
        float v0, v1;
        unpack2(acc, v0, v1);
        int gr0 = r0 + 2 * p;
        if (gr0 < N_NODES)     out[(size_t)gr0 * F1 + t] = v0;
        if (gr0 + 1 < N_NODES) out[(size_t)(gr0 + 1) * F1 + t] = v1;
    }
}

// ---------------- scores v2: one WARP per NODE, coalesced float4 reads ----------------
template<int H>
__global__ void scores_kernel(const float* __restrict__ h,
                              const float* __restrict__ asrc,
                              const float* __restrict__ adst,
                              float* __restrict__ ss, float* __restrict__ sd) {
    int gid = blockIdx.x * blockDim.x + threadIdx.x;
    int n = gid >> 5, lane = gid & 31;
    if (n >= N_NODES) return;
    const float4* h4  = (const float4*)(h + (size_t)n * (H * 64));
    const float4* as4 = (const float4*)asrc;
    const float4* ad4 = (const float4*)adst;

    float4 v0 = h4[lane];
    float4 a0 = as4[lane], d0 = ad4[lane];
    float sa0 = v0.x * a0.x + v0.y * a0.y + v0.z * a0.z + v0.w * a0.w;
    float sd0 = v0.x * d0.x + v0.y * d0.y + v0.z * d0.z + v0.w * d0.w;
    float sa1 = 0.f, sd1 = 0.f;
    if (H == 4) {
        float4 v1 = h4[lane + 32];
        float4 a1 = as4[lane + 32], d1 = ad4[lane + 32];
        sa1 = v1.x * a1.x + v1.y * a1.y + v1.z * a1.z + v1.w * a1.w;
        sd1 = v1.x * d1.x + v1.y * d1.y + v1.z * d1.z + v1.w * d1.w;
    }
#pragma unroll
    for (int o = 8; o > 0; o >>= 1) {
        sa0 += __shfl_down_sync(0xffffffffu, sa0, o, 16);
        sd0 += __shfl_down_sync(0xffffffffu, sd0, o, 16);
        if (H == 4) {
            sa1 += __shfl_down_sync(0xffffffffu, sa1, o, 16);
            sd1 += __shfl_down_sync(0xffffffffu, sd1, o, 16);
        }
    }
    if (H == 4) {
        if (lane == 0)  { ss[n * 4 + 0] = sa0; sd[n * 4 + 0] = sd0;
                          ss[n * 4 + 2] = sa1; sd[n * 4 + 2] = sd1; }
        if (lane == 16) { ss[n * 4 + 1] = sa0; sd[n * 4 + 1] = sd0;
                          ss[n * 4 + 3] = sa1; sd[n * 4 + 3] = sd1; }
    } else {
        if (lane == 0)  { ss[n * 2 + 0] = sa0; sd[n * 2 + 0] = sd0; }
        if (lane == 16) { ss[n * 2 + 1] = sa0; sd[n * 2 + 1] = sd0; }
    }
}

// ---------------- edge pass (atomic/RED): z += e ; agg += e * h[src] ----------------
template<int H, int F>
__global__ void edge_agg_kernel(const int* __restrict__ ei, int E, int ET,
                                const float* __restrict__ ss,
                                const float* __restrict__ sd,
                                float* __restrict__ z,
                                const float* __restrict__ h,
                                float* __restrict__ agg) {
    int gid = blockIdx.x * blockDim.x + threadIdx.x;
    int e = gid >> 5, lane = gid & 31;
    if (e >= ET) return;
    int src, dst;
    if (e < E) { src = ei[e]; dst = ei[E + e]; }
    else       { src = dst = e - E; }
    float ev = 0.f;
    if (lane < H) {
        float l = ss[src * H + lane] + sd[dst * H + lane];
        l = (l > 0.f) ? l : 0.2f * l;
        ev = __expf(l);
        atomicAdd(&z[dst * H + lane], ev);
    }
    const float4* hs = (const float4*)(h + (size_t)src * F);
    float* ag = agg + (size_t)dst * F;
#pragma unroll
    for (int i = 0; i < F / 128; i++) {
        int f = lane + i * 32;
        float evc = __shfl_sync(0xffffffffu, ev, f >> 4);
        float4 v = hs[f];
        v.x *= evc; v.y *= evc; v.z *= evc; v.w *= evc;
        red_add_f4(ag + f * 4, v);
    }
}

// ---------------- GEMM2 (f32x2, double-buffered, cp.async B, 2 CTAs/SM) with FUSED
// layer-1 finalize on A-load: A_eff = elu(agg1/(z1+eps)+b1); C = A_eff @ W2 ----------------
// smem: As2 [2][16][132] u64 (33792B) + Bs [2][16][128] f32 (16384B) = 50176B
#define G2_SMEM_A   0
#define G2_SMEM_B   33792
#define G2_SMEM_TOT (33792 + 16384)

__global__ void __launch_bounds__(256, 2)
gemm2_db_kernel(const float* __restrict__ A,
                const float* __restrict__ zA,
                const float* __restrict__ bA,
                const float* __restrict__ B,
                float* __restrict__ C) {
    extern __shared__ char smem[];
    unsigned long long* As2 = (unsigned long long*)(smem + G2_SMEM_A);
    const unsigned long long* Bs2 = (const unsigned long long*)(smem + G2_SMEM_B);
    uint32_t bs_base = smem_u32(smem + G2_SMEM_B);

    int t = threadIdx.x;            // 256 threads
    int tx = t & 15, ty = t >> 4;
    int row0 = blockIdx.x * 128;

    unsigned long long acc[8][4];
#pragma unroll
    for (int i = 0; i < 8; i++)
#pragma unroll
        for (int q = 0; q < 4; q++) acc[i][q] = 0ULL;

    // A staging coords: idx = t + s*256 -> r = idx>>2, kq = idx&3
    int r_[2], kq_[2], gr_[2];
#pragma unroll
    for (int s = 0; s < 2; s++) {
        int idx = t + s * 256;
        r_[s] = idx >> 2; kq_[s] = idx & 3;
        gr_[s] = row0 + r_[s];
    }
    // B cp.async coords: float4 idx = t + s*256 -> k = idx>>5, c4 = idx&31
    float4 g[2], bb[2];
    float  rz[2];

    // prologue: tile 0
#pragma unroll
    for (int s = 0; s < 2; s++) {
        int c = kq_[s] * 4;
        if (gr_[s] < N_NODES) {
            g[s]  = *(const float4*)&A[(size_t)gr_[s] * 256 + c];
            bb[s] = *(const float4*)&bA[c];
            rz[s] = __fdividef(1.f, zA[gr_[s] * H1 + (c >> 6)] + 1e-16f);
        }
        int idx = t + s * 256;
        CP_ASYNC16(bs_base + (uint32_t)idx * 16u,
                   &B[(size_t)(idx >> 5) * 128 + (idx & 31) * 4]);
    }
    CP_COMMIT();
#pragma unroll
    for (int s = 0; s < 2; s++) {
        float4 v = make_float4(0.f, 0.f, 0.f, 0.f);
        if (gr_[s] < N_NODES) {
            v.x = elu_fast(fmaf(g[s].x, rz[s], bb[s].x));
            v.y = elu_fast(fmaf(g[s].y, rz[s], bb[s].y));
            v.z = elu_fast(fmaf(g[s].z, rz[s], bb[s].z));
            v.w = elu_fast(fmaf(g[s].w, rz[s], bb[s].w));
        }
        unsigned long long* dst = As2 + (kq_[s] * 4) * 132 + r_[s];
        dst[0 * 132] = rep2(v.x); dst[1 * 132] = rep2(v.y);
        dst[2 * 132] = rep2(v.z); dst[3 * 132] = rep2(v.w);
    }
    CP_WAIT0();
    __syncthreads();

    for (int kt = 0; kt < 16; kt++) {
        // prefetch next tile while computing this one
        if (kt < 15) {
#pragma unroll
            for (int s = 0; s < 2; s++) {
                int c = (kt + 1) * 16 + kq_[s] * 4;
                if (gr_[s] < N_NODES) {
                    g[s]  = *(const float4*)&A[(size_t)gr_[s] * 256 + c];
                    bb[s] = *(const float4*)&bA[c];
                    rz[s] = __fdividef(1.f, zA[gr_[s] * H1 + (c >> 6)] + 1e-16f);
                }
                int idx = t + s * 256;
                CP_ASYNC16(bs_base + (((uint32_t)((kt + 1) & 1) * 512u + (uint32_t)idx) * 16u),
                           &B[(size_t)((kt + 1) * 16 + (idx >> 5)) * 128 + (idx & 31) * 4]);
            }
            CP_COMMIT();
        }
        // compute from buffer kt&1
        const unsigned long long* A2 = As2 + (kt & 1) * (16 * 132);
        const unsigned long long* B2 = Bs2 + (kt & 1) * 1024;   // 16*128 f32 = 1024 u64
#pragma unroll
        for (int k = 0; k < 16; k++) {
            unsigned long long a2[8], b2[4];
#pragma unroll
            for (int i = 0; i < 8; i++) a2[i] = A2[k * 132 + ty * 8 + i];
#pragma unroll
            for (int j = 0; j < 4; j++)
                b2[j] = B2[k * 64 + tx * 4 + j];   // contiguous -> 2x LDS.128
#pragma unroll
            for (int i = 0; i < 8; i++)
#pragma unroll
                for (int j = 0; j < 4; j++)
                    FMA2(acc[i][j], a2[i], b2[j]);
        }
        // store next A tile into buffer (kt+1)&1
        if (kt < 15) {
            unsigned long long* dstbuf = As2 + ((kt + 1) & 1) * (16 * 132);
#pragma unroll
            for (int s = 0; s < 2; s++) {
                float4 v = make_float4(0.f, 0.f, 0.f, 0.f);
                if (gr_[s] < N_NODES) {
                    v.x = elu_fast(fmaf(g[s].x, rz[s], bb[s].x));
                    v.y = elu_fast(fmaf(g[s].y, rz[s], bb[s].y));
                    v.z = elu_fast(fmaf(g[s].z, rz[s], bb[s].z));
                    v.w = elu_fast(fmaf(g[s].w, rz[s], bb[s].w));
                }
                unsigned long long* dst = dstbuf + (kq_[s] * 4) * 132 + r_[s];
                dst[0 * 132] = rep2(v.x); dst[1 * 132] = rep2(v.y);
                dst[2 * 132] = rep2(v.z); dst[3 * 132] = rep2(v.w);
            }
            CP_WAIT0();
            __syncthreads();
        }
    }

    // writeback: thread owns rows row0+ty*8+i, cols 8*tx..8*tx+7 (contiguous)
#pragma unroll
    for (int i = 0; i < 8; i++) {
        int gr = row0 + ty * 8 + i;
        if (gr >= N_NODES) continue;
        ulonglong2 w0; w0.x = acc[i][0]; w0.y = acc[i][1];
        ulonglong2 w1; w1.x = acc[i][2]; w1.y = acc[i][3];
        *(ulonglong2*)&C[(size_t)gr * 128 + 8 * tx]     = w0;
        *(ulonglong2*)&C[(size_t)gr * 128 + 8 * tx + 4] = w1;
    }
}

// ---------------- final (FUSED layer-2 finalize):
// out = sigmoid( elu(agg2/(z2+eps)+b2) @ Wfc + bfc ) ----------------
__global__ void out_fused_kernel(const float* __restrict__ agg,
                                 const float* __restrict__ z,
                                 const float* __restrict__ b,
                                 const float* __restrict__ Wfc,
                                 const float* __restrict__ bfc,
                                 float* __restrict__ out) {
    int gid = blockIdx.x * blockDim.x + threadIdx.x;
    int n = gid >> 5, lane = gid & 31;
    if (n >= N_NODES) return;
    const float* hp = agg + (size_t)n * 128;
    float rz0 = __fdividef(1.f, z[n * H2 + 0] + 1e-16f);
    float rz1 = __fdividef(1.f, z[n * H2 + 1] + 1e-16f);
    float v0 = elu_fast(fmaf(hp[lane],      rz0, b[lane]));
    float v1 = elu_fast(fmaf(hp[lane + 32], rz0, b[lane + 32]));
    float v2 = elu_fast(fmaf(hp[lane + 64], rz1, b[lane + 64]));
    float v3 = elu_fast(fmaf(hp[lane + 96], rz1, b[lane + 96]));
    float s = v0 * Wfc[lane] + v1 * Wfc[lane + 32]
            + v2 * Wfc[lane + 64] + v3 * Wfc[lane + 96];
#pragma unroll
    for (int o = 16; o > 0; o >>= 1) s += __shfl_down_sync(0xffffffffu, s, o);
    if (lane == 0) {
        float v = s + bfc[0];
        out[n] = 1.f / (1.f + __expf(-v));
    }
}

// ---------------- launch ----------------
extern "C" void kernel_launch(void* const* d_in, const int* in_sizes, int n_in,
                              void* d_out, int out_size) {
    const float* x      = (const float*)d_in[0];
    const int*   ei     = (const int*)  d_in[1];
    const float* W1     = (const float*)d_in[2];
    const float* a_src1 = (const float*)d_in[3];
    const float* a_dst1 = (const float*)d_in[4];
    const float* b1     = (const float*)d_in[5];
    const float* W2     = (const float*)d_in[6];
    const float* a_src2 = (const float*)d_in[7];
    const float* a_dst2 = (const float*)d_in[8];
    const float* b2     = (const float*)d_in[9];
    const float* Wfc    = (const float*)d_in[10];
    const float* bfc    = (const float*)d_in[11];
    float* out = (float*)d_out;

    int E  = in_sizes[1] / 2;
    int ET = E + N_NODES;

    float *h1, *agg1, *h2, *agg2, *ss, *sd;
    cudaGetSymbolAddress((void**)&h1,   g_h1);
    cudaGetSymbolAddress((void**)&agg1, g_agg1);
    cudaGetSymbolAddress((void**)&h2,   g_h2);
    cudaGetSymbolAddress((void**)&agg2, g_agg2);
    cudaGetSymbolAddress((void**)&ss,   g_ss);
    cudaGetSymbolAddress((void**)&sd,   g_sd);
    float* z1 = agg1 + (size_t)N_NODES * F1;   // z appended to agg buffers
    float* z2 = agg2 + (size_t)N_NODES * F2;

    cudaFuncSetAttribute(gemm2_db_kernel,
                         cudaFuncAttributeMaxDynamicSharedMemorySize, G2_SMEM_TOT);

    const int TB = 256;

    // ===== layer 1 (H=4, F=256) =====
    gemm1_kernel<<<(N_NODES + 63) / 64, TB>>>(x, W1, h1);
    scores_kernel<H1><<<(N_NODES * 32 + TB - 1) / TB, TB>>>(h1, a_src1, a_dst1, ss, sd);
    cudaMemsetAsync(agg1, 0, (size_t)N_NODES * (F1 + H1) * sizeof(float));
    edge_agg_kernel<H1, F1><<<(ET * 32 + TB - 1) / TB, TB>>>(ei, E, ET, ss, sd, z1, h1, agg1);

    // ===== layer 2 (H=2, F=128): gemm2 fuses layer-1 normalize+bias+elu =====
    gemm2_db_kernel<<<(N_NODES + 127) / 128, TB, G2_SMEM_TOT>>>(agg1, z1, b1, W2, h2);
    scores_kernel<H2><<<(N_NODES * 32 + TB - 1) / TB, TB>>>(h2, a_src2, a_dst2, ss, sd);
    cudaMemsetAsync(agg2, 0, (size_t)N_NODES * (F2 + H2) * sizeof(float));
    edge_agg_kernel<H2, F2><<<(ET * 32 + TB - 1) / TB, TB>>>(ei, E, ET, ss, sd, z2, h2, agg2);

    // ===== final: fuses layer-2 normalize+bias+elu with the 128->1 dot =====
    out_fused_kernel<<<(N_NODES * 32 + TB - 1) / TB, TB>>>(agg2, z2, b2, Wfc, bfc, out);
}

// round 15
// speedup vs baseline: 1.0781x; 1.0781x over previous
#include <cuda_runtime.h>
#include <math.h>
#include <stdint.h>

#define N_NODES 50000
#define IN_DIM  27
#define F1      256
#define H1      4
#define F2      128
#define H2      2

// ---------------- scratch (no allocations allowed) ----------------
__device__ float g_h1  [N_NODES * F1];
__device__ float g_agg1[N_NODES * (F1 + H1)];   // agg1 + z1 appended
__device__ float g_h2  [N_NODES * F2];
__device__ float g_agg2[N_NODES * (F2 + H2)];   // agg2 + z2 appended
__device__ float g_ss  [N_NODES * H1];
__device__ float g_sd  [N_NODES * H1];

__device__ __forceinline__ void red_add_f4(float* p, float4 v) {
    asm volatile("red.global.add.v4.f32 [%0], {%1, %2, %3, %4};"
                 :: "l"(p), "f"(v.x), "f"(v.y), "f"(v.z), "f"(v.w) : "memory");
}

__device__ __forceinline__ float elu_fast(float v) {
    return (v > 0.f) ? v : (__expf(v) - 1.f);
}

// packed f32x2 helpers (plain sm_100+ PTX, not an 'a' feature)
__device__ __forceinline__ unsigned long long rep2(float x) {
    unsigned long long r;
    asm("mov.b64 %0, {%1, %1};" : "=l"(r) : "f"(x));
    return r;
}
__device__ __forceinline__ void unpack2(unsigned long long v, float& a, float& b) {
    asm("mov.b64 {%0, %1}, %2;" : "=f"(a), "=f"(b) : "l"(v));
}
#define FMA2(d, a, b) \
    asm("fma.rn.f32x2 %0, %1, %2, %0;" : "+l"(d) : "l"(a), "l"(b))

// ---------------- GEMM1 (f32x2 row pairs): x[N,27] @ W1[27,256] -> h1[N,256] ----------------
__global__ void __launch_bounds__(256)
gemm1_kernel(const float* __restrict__ x,
             const float* __restrict__ W,
             float* __restrict__ out) {
    __shared__ float Ws[IN_DIM * F1];       // 27KB
    __shared__ float xs[IN_DIM * 64];       // transposed: xs[k][r]
    int t = threadIdx.x;                    // 256 threads
    for (int i = t; i < IN_DIM * F1; i += 256) Ws[i] = W[i];
    int r0 = blockIdx.x * 64;
    for (int i = t; i < IN_DIM * 64; i += 256) {
        int k = i >> 6, r = i & 63;
        int gr = r0 + r;
        xs[k * 64 + r] = (gr < N_NODES) ? x[gr * IN_DIM + k] : 0.f;
    }
    __syncthreads();

    unsigned long long w2[IN_DIM];
#pragma unroll
    for (int k = 0; k < IN_DIM; k++) w2[k] = rep2(Ws[k * F1 + t]);

#pragma unroll 4
    for (int p = 0; p < 32; p++) {          // row pair (2p, 2p+1)
        unsigned long long acc = 0ULL;
#pragma unroll
        for (int k = 0; k < IN_DIM; k++) {
            unsigned long long xp = *(const unsigned long long*)&xs[k * 64 + 2 * p];
            FMA2(acc, xp, w2[k]);
        }
        float v0, v1;
        unpack2(acc, v0, v1);
        int gr0 = r0 + 2 * p;
        if (gr0 < N_NODES)     out[(size_t)gr0 * F1 + t] = v0;
        if (gr0 + 1 < N_NODES) out[(size_t)(gr0 + 1) * F1 + t] = v1;
    }
}

// ---------------- scores v2: one WARP per NODE, coalesced float4 reads ----------------
template<int H>
__global__ void scores_kernel(const float* __restrict__ h,
                              const float* __restrict__ asrc,
                              const float* __restrict__ adst,
                              float* __restrict__ ss, float* __restrict__ sd) {
    int gid = blockIdx.x * blockDim.x + threadIdx.x;
    int n = gid >> 5, lane = gid & 31;
    if (n >= N_NODES) return;
    const float4* h4  = (const float4*)(h + (size_t)n * (H * 64));
    const float4* as4 = (const float4*)asrc;
    const float4* ad4 = (const float4*)adst;

    float4 v0 = h4[lane];
    float4 a0 = as4[lane], d0 = ad4[lane];
    float sa0 = v0.x * a0.x + v0.y * a0.y + v0.z * a0.z + v0.w * a0.w;
    float sd0 = v0.x * d0.x + v0.y * d0.y + v0.z * d0.z + v0.w * d0.w;
    float sa1 = 0.f, sd1 = 0.f;
    if (H == 4) {
        float4 v1 = h4[lane + 32];
        float4 a1 = as4[lane + 32], d1 = ad4[lane + 32];
        sa1 = v1.x * a1.x + v1.y * a1.y + v1.z * a1.z + v1.w * a1.w;
        sd1 = v1.x * d1.x + v1.y * d1.y + v1.z * d1.z + v1.w * d1.w;
    }
#pragma unroll
    for (int o = 8; o > 0; o >>= 1) {
        sa0 += __shfl_down_sync(0xffffffffu, sa0, o, 16);
        sd0 += __shfl_down_sync(0xffffffffu, sd0, o, 16);
        if (H == 4) {
            sa1 += __shfl_down_sync(0xffffffffu, sa1, o, 16);
            sd1 += __shfl_down_sync(0xffffffffu, sd1, o, 16);
        }
    }
    if (H == 4) {
        if (lane == 0)  { ss[n * 4 + 0] = sa0; sd[n * 4 + 0] = sd0;
                          ss[n * 4 + 2] = sa1; sd[n * 4 + 2] = sd1; }
        if (lane == 16) { ss[n * 4 + 1] = sa0; sd[n * 4 + 1] = sd0;
                          ss[n * 4 + 3] = sa1; sd[n * 4 + 3] = sd1; }
    } else {
        if (lane == 0)  { ss[n * 2 + 0] = sa0; sd[n * 2 + 0] = sd0; }
        if (lane == 16) { ss[n * 2 + 1] = sa0; sd[n * 2 + 1] = sd0; }
    }
}

// ---------------- edge pass (atomic/RED): z += e ; agg += e * h[src] ----------------
template<int H, int F>
__global__ void edge_agg_kernel(const int* __restrict__ ei, int E, int ET,
                                const float* __restrict__ ss,
                                const float* __restrict__ sd,
                                float* __restrict__ z,
                                const float* __restrict__ h,
                                float* __restrict__ agg) {
    int gid = blockIdx.x * blockDim.x + threadIdx.x;
    int e = gid >> 5, lane = gid & 31;
    if (e >= ET) return;
    int src, dst;
    if (e < E) { src = ei[e]; dst = ei[E + e]; }
    else       { src = dst = e - E; }
    float ev = 0.f;
    if (lane < H) {
        float l = ss[src * H + lane] + sd[dst * H + lane];
        l = (l > 0.f) ? l : 0.2f * l;
        ev = __expf(l);
        atomicAdd(&z[dst * H + lane], ev);
    }
    const float4* hs = (const float4*)(h + (size_t)src * F);
    float* ag = agg + (size_t)dst * F;
#pragma unroll
    for (int i = 0; i < F / 128; i++) {
        int f = lane + i * 32;
        float evc = __shfl_sync(0xffffffffu, ev, f >> 4);
        float4 v = hs[f];
        v.x *= evc; v.y *= evc; v.z *= evc; v.w *= evc;
        red_add_f4(ag + f * 4, v);
    }
}

// ---------------- GEMM2 (f32x2, double-buffered A AND B via LDG, 2 CTAs/SM) with
// FUSED layer-1 finalize on A-load: A_eff = elu(agg1/(z1+eps)+b1); C = A_eff @ W2
// (exact R13-measured 108.5us version) ----------------
// smem: As2 [2][16][132] u64 (33792B) + Bs [2][16][128] f32 (16384B) = 50176B
#define G2_SMEM_A   0
#define G2_SMEM_B   33792
#define G2_SMEM_TOT (33792 + 16384)

__global__ void __launch_bounds__(256, 2)
gemm2_db_kernel(const float* __restrict__ A,
                const float* __restrict__ zA,
                const float* __restrict__ bA,
                const float* __restrict__ B,
                float* __restrict__ C) {
    extern __shared__ char smem[];
    unsigned long long* As2 = (unsigned long long*)(smem + G2_SMEM_A);
    float* Bs = (float*)(smem + G2_SMEM_B);
    const unsigned long long* Bs2 = (const unsigned long long*)Bs;

    int t = threadIdx.x;            // 256 threads
    int tx = t & 15, ty = t >> 4;
    int row0 = blockIdx.x * 128;

    unsigned long long acc[8][4];
#pragma unroll
    for (int i = 0; i < 8; i++)
#pragma unroll
        for (int q = 0; q < 4; q++) acc[i][q] = 0ULL;

    // A staging coords: idx = t + s*256 -> r = idx>>2, kq = idx&3
    int r_[2], kq_[2], gr_[2];
#pragma unroll
    for (int s = 0; s < 2; s++) {
        int idx = t + s * 256;
        r_[s] = idx >> 2; kq_[s] = idx & 3;
        gr_[s] = row0 + r_[s];
    }
    // B staging coords: idx = t + s*256 (float4 units) -> k = idx>>5, c4 = idx&31
    int bk_[2], bc_[2];
#pragma unroll
    for (int s = 0; s < 2; s++) {
        int idx = t + s * 256;
        bk_[s] = idx >> 5; bc_[s] = idx & 31;
    }

    float4 g[2], bb[2], bg[2];
    float  rz[2];

    // prefetch tile 0 (A + B)
#pragma unroll
    for (int s = 0; s < 2; s++) {
        int c = kq_[s] * 4;
        if (gr_[s] < N_NODES) {
            g[s]  = *(const float4*)&A[(size_t)gr_[s] * 256 + c];
            bb[s] = *(const float4*)&bA[c];
            rz[s] = __fdividef(1.f, zA[gr_[s] * H1 + (c >> 6)] + 1e-16f);
        }
        bg[s] = *(const float4*)&B[(size_t)bk_[s] * 128 + bc_[s] * 4];
    }
    // store tile 0 into buf 0
#pragma unroll
    for (int s = 0; s < 2; s++) {
        float4 v = make_float4(0.f, 0.f, 0.f, 0.f);
        if (gr_[s] < N_NODES) {
            v.x = elu_fast(fmaf(g[s].x, rz[s], bb[s].x));
            v.y = elu_fast(fmaf(g[s].y, rz[s], bb[s].y));
            v.z = elu_fast(fmaf(g[s].z, rz[s], bb[s].z));
            v.w = elu_fast(fmaf(g[s].w, rz[s], bb[s].w));
        }
        unsigned long long* dst = As2 + (kq_[s] * 4) * 132 + r_[s];
        dst[0 * 132] = rep2(v.x); dst[1 * 132] = rep2(v.y);
        dst[2 * 132] = rep2(v.z); dst[3 * 132] = rep2(v.w);
        ((float4*)Bs)[t + s * 256] = bg[s];
    }
    __syncthreads();

    for (int kt = 0; kt < 16; kt++) {
        // prefetch next tile (A + B) while computing this one
        if (kt < 15) {
#pragma unroll
            for (int s = 0; s < 2; s++) {
                int c = (kt + 1) * 16 + kq_[s] * 4;
                if (gr_[s] < N_NODES) {
                    g[s]  = *(const float4*)&A[(size_t)gr_[s] * 256 + c];
                    bb[s] = *(const float4*)&bA[c];
                    rz[s] = __fdividef(1.f, zA[gr_[s] * H1 + (c >> 6)] + 1e-16f);
                }
                bg[s] = *(const float4*)&B[(size_t)((kt + 1) * 16 + bk_[s]) * 128 + bc_[s] * 4];
            }
        }
        // compute from buffer kt&1
        const unsigned long long* A2 = As2 + (kt & 1) * (16 * 132);
        const unsigned long long* B2 = Bs2 + (kt & 1) * 1024;   // 16*128 f32 = 1024 u64
#pragma unroll
        for (int k = 0; k < 16; k++) {
            unsigned long long a2[8], b2[4];
#pragma unroll
            for (int i = 0; i < 8; i++) a2[i] = A2[k * 132 + ty * 8 + i];
#pragma unroll
            for (int q = 0; q < 4; q++)
                b2[q] = B2[k * 64 + tx + q * 16];
#pragma unroll
            for (int i = 0; i < 8; i++)
#pragma unroll
                for (int q = 0; q < 4; q++)
                    FMA2(acc[i][q], a2[i], b2[q]);
        }
        // store next tile into buffer (kt+1)&1
        if (kt < 15) {
            unsigned long long* dstbuf = As2 + ((kt + 1) & 1) * (16 * 132);
            float4* bdst = (float4*)(Bs + ((kt + 1) & 1) * 2048);
#pragma unroll
            for (int s = 0; s < 2; s++) {
                float4 v = make_float4(0.f, 0.f, 0.f, 0.f);
                if (gr_[s] < N_NODES) {
                    v.x = elu_fast(fmaf(g[s].x, rz[s], bb[s].x));
                    v.y = elu_fast(fmaf(g[s].y, rz[s], bb[s].y));
                    v.z = elu_fast(fmaf(g[s].z, rz[s], bb[s].z));
                    v.w = elu_fast(fmaf(g[s].w, rz[s], bb[s].w));
                }
                unsigned long long* dst = dstbuf + (kq_[s] * 4) * 132 + r_[s];
                dst[0 * 132] = rep2(v.x); dst[1 * 132] = rep2(v.y);
                dst[2 * 132] = rep2(v.z); dst[3 * 132] = rep2(v.w);
                bdst[t + s * 256] = bg[s];
            }
            __syncthreads();
        }
    }

    // writeback: thread owns rows row0+ty*8+i, column pairs p = tx+16q -> cols 2p,2p+1
#pragma unroll
    for (int i = 0; i < 8; i++) {
        int gr = row0 + ty * 8 + i;
        if (gr >= N_NODES) continue;
#pragma unroll
        for (int q = 0; q < 4; q++)
            *(unsigned long long*)&C[(size_t)gr * 128 + 2 * (tx + 16 * q)] = acc[i][q];
    }
}

// ---------------- final (FUSED layer-2 finalize):
// out = sigmoid( elu(agg2/(z2+eps)+b2) @ Wfc + bfc ) ----------------
__global__ void out_fused_kernel(const float* __restrict__ agg,
                                 const float* __restrict__ z,
                                 const float* __restrict__ b,
                                 const float* __restrict__ Wfc,
                                 const float* __restrict__ bfc,
                                 float* __restrict__ out) {
    int gid = blockIdx.x * blockDim.x + threadIdx.x;
    int n = gid >> 5, lane = gid & 31;
    if (n >= N_NODES) return;
    const float* hp = agg + (size_t)n * 128;
    float rz0 = __fdividef(1.f, z[n * H2 + 0] + 1e-16f);
    float rz1 = __fdividef(1.f, z[n * H2 + 1] + 1e-16f);
    float v0 = elu_fast(fmaf(hp[lane],      rz0, b[lane]));
    float v1 = elu_fast(fmaf(hp[lane + 32], rz0, b[lane + 32]));
    float v2 = elu_fast(fmaf(hp[lane + 64], rz1, b[lane + 64]));
    float v3 = elu_fast(fmaf(hp[lane + 96], rz1, b[lane + 96]));
    float s = v0 * Wfc[lane] + v1 * Wfc[lane + 32]
            + v2 * Wfc[lane + 64] + v3 * Wfc[lane + 96];
#pragma unroll
    for (int o = 16; o > 0; o >>= 1) s += __shfl_down_sync(0xffffffffu, s, o);
    if (lane == 0) {
        float v = s + bfc[0];
        out[n] = 1.f / (1.f + __expf(-v));
    }
}

// ---------------- launch ----------------
extern "C" void kernel_launch(void* const* d_in, const int* in_sizes, int n_in,
                              void* d_out, int out_size) {
    const float* x      = (const float*)d_in[0];
    const int*   ei     = (const int*)  d_in[1];
    const float* W1     = (const float*)d_in[2];
    const float* a_src1 = (const float*)d_in[3];
    const float* a_dst1 = (const float*)d_in[4];
    const float* b1     = (const float*)d_in[5];
    const float* W2     = (const float*)d_in[6];
    const float* a_src2 = (const float*)d_in[7];
    const float* a_dst2 = (const float*)d_in[8];
    const float* b2     = (const float*)d_in[9];
    const float* Wfc    = (const float*)d_in[10];
    const float* bfc    = (const float*)d_in[11];
    float* out = (float*)d_out;

    int E  = in_sizes[1] / 2;
    int ET = E + N_NODES;

    float *h1, *agg1, *h2, *agg2, *ss, *sd;
    cudaGetSymbolAddress((void**)&h1,   g_h1);
    cudaGetSymbolAddress((void**)&agg1, g_agg1);
    cudaGetSymbolAddress((void**)&h2,   g_h2);
    cudaGetSymbolAddress((void**)&agg2, g_agg2);
    cudaGetSymbolAddress((void**)&ss,   g_ss);
    cudaGetSymbolAddress((void**)&sd,   g_sd);
    float* z1 = agg1 + (size_t)N_NODES * F1;   // z appended to agg buffers
    float* z2 = agg2 + (size_t)N_NODES * F2;

    cudaFuncSetAttribute(gemm2_db_kernel,
                         cudaFuncAttributeMaxDynamicSharedMemorySize, G2_SMEM_TOT);

    const int TB = 256;

    // ===== layer 1 (H=4, F=256) =====
    gemm1_kernel<<<(N_NODES + 63) / 64, TB>>>(x, W1, h1);
    scores_kernel<H1><<<(N_NODES * 32 + TB - 1) / TB, TB>>>(h1, a_src1, a_dst1, ss, sd);
    cudaMemsetAsync(agg1, 0, (size_t)N_NODES * (F1 + H1) * sizeof(float));
    edge_agg_kernel<H1, F1><<<(ET * 32 + TB - 1) / TB, TB>>>(ei, E, ET, ss, sd, z1, h1, agg1);

    // ===== layer 2 (H=2, F=128): gemm2 fuses layer-1 normalize+bias+elu =====
    gemm2_db_kernel<<<(N_NODES + 127) / 128, TB, G2_SMEM_TOT>>>(agg1, z1, b1, W2, h2);
    scores_kernel<H2><<<(N_NODES * 32 + TB - 1) / TB, TB>>>(h2, a_src2, a_dst2, ss, sd);
    cudaMemsetAsync(agg2, 0, (size_t)N_NODES * (F2 + H2) * sizeof(float));
    edge_agg_kernel<H2, F2><<<(ET * 32 + TB - 1) / TB, TB>>>(ei, E, ET, ss, sd, z2, h2, agg2);

    // ===== final: fuses layer-2 normalize+bias+elu with the 128->1 dot =====
    out_fused_kernel<<<(N_NODES * 32 + TB - 1) / TB, TB>>>(agg2, z2, b2, Wfc, bfc, out);
}